// round 15
// baseline (speedup 1.0000x reference)
#include <cuda_runtime.h>
#include <cuda_bf16.h>
#include <math.h>
#include <stdint.h>

#define LL    384
#define NPIX  (LL*LL)
#define HID   64
#define BINS  63
#define ADIM  32
#define NANCH 32
#define ASTRIDE 12

// ---------------- scratch ------------------------------------------------------
__device__ float g_x[HID*NPIX];
__device__ float g_a[HID*NPIX];
__device__ float g_b[HID*NPIX];
__device__ __nv_bfloat16 g_h[NPIX*64];
__device__ __nv_bfloat16 g_l[NPIX*64];
__device__ __nv_bfloat16 g_wh[15*9*64*64];
__device__ __nv_bfloat16 g_wl[15*9*64*64];
__device__ float g_left [LL*NANCH*ADIM];
__device__ float g_right[ADIM*NANCH*LL];    // [a][k][p] coalesced for attn
__device__ float g_vleft [LL*NANCH*ADIM];
__device__ float g_vright[ADIM*NANCH*LL];
__device__ float g_mean[HID];
__device__ float g_rstd[HID];
__device__ double g_ssum[HID];
__device__ double g_ssq[HID];
__device__ float g_gate;

// ---------------- helpers ------------------------------------------------------
__device__ __forceinline__ uint32_t smem_u32(const void* p) {
    uint32_t a;
    asm("{ .reg .u64 t; cvta.to.shared.u64 t, %1; cvt.u32.u64 %0, t; }" : "=r"(a) : "l"(p));
    return a;
}
__device__ __forceinline__ void ldm_x4(uint32_t* r, uint32_t addr) {
    asm volatile("ldmatrix.sync.aligned.m8n8.x4.shared.b16 {%0,%1,%2,%3}, [%4];"
        : "=r"(r[0]), "=r"(r[1]), "=r"(r[2]), "=r"(r[3]) : "r"(addr));
}
__device__ __forceinline__ void mma_bf16(float* c, const uint32_t* a, const uint32_t* b) {
    asm volatile(
        "mma.sync.aligned.m16n8k16.row.col.f32.bf16.bf16.f32 "
        "{%0,%1,%2,%3}, {%4,%5,%6,%7}, {%8,%9}, {%0,%1,%2,%3};"
        : "+f"(c[0]), "+f"(c[1]), "+f"(c[2]), "+f"(c[3])
        : "r"(a[0]), "r"(a[1]), "r"(a[2]), "r"(a[3]), "r"(b[0]), "r"(b[1]));
}
__device__ __forceinline__ void cpa16(uint32_t d, const void* s, int sz) {
    asm volatile("cp.async.cg.shared.global [%0], [%1], 16, %2;"
        :: "r"(d), "l"(s), "r"(sz) : "memory");
}
__device__ __forceinline__ void cpa_commit() {
    asm volatile("cp.async.commit_group;" ::: "memory");
}
__device__ __forceinline__ void cpa_wait1() {
    asm volatile("cp.async.wait_group 1;" ::: "memory");
}
__device__ __forceinline__ void cpa_wait0() {
    asm volatile("cp.async.wait_group 0;" ::: "memory");
}
__device__ __forceinline__ float fast_sigmoid(float v) {
    return 1.f / (1.f + __expf(-v));
}

// ---------------- weight split -------------------------------------------------
__global__ void k_wsplit(const float* __restrict__ src, int slot0, int OC, int IC) {
    int t = blockIdx.x, s = blockIdx.y;
    const float* w = src + (size_t)s * OC * IC * 9;
    __nv_bfloat16* dh = g_wh + ((size_t)(slot0 + s) * 9 + t) * 4096;
    __nv_bfloat16* dl = g_wl + ((size_t)(slot0 + s) * 9 + t) * 4096;
    for (int idx = threadIdx.x; idx < 4096; idx += 256) {
        int oc = idx >> 6, ic = idx & 63;
        float v = (oc < OC && ic < IC) ? w[((size_t)oc * IC + ic) * 9 + t] : 0.f;
        __nv_bfloat16 h = __float2bfloat16(v);
        dh[idx] = h;
        dl[idx] = __float2bfloat16(v - __bfloat162float(h));
    }
}

// ---------------- HMMA 3x3 conv, M=128 tile, slab-shared A + dbuf B ----------------
#define SLAB_H 0
#define SLAB_L 20480
#define BH(p) (40960 + (p)*16384)
#define BL(p) (40960 + (p)*16384 + 8192)
#define SMEM_T 73728

__global__ void __launch_bounds__(256, 3)
k_tconv(const __nv_bfloat16* __restrict__ xh, const __nv_bfloat16* __restrict__ xl,
        const __nv_bfloat16* __restrict__ wh, const __nv_bfloat16* __restrict__ wl,
        const float* __restrict__ bias, float* __restrict__ out,
        int OC, int d, int act, int stats,
        const float* __restrict__ conf_w, const float* __restrict__ conf_b) {
    extern __shared__ __align__(16) char smem[];
    __shared__ float s_sum[64], s_sq[64];
    uint32_t sb = smem_u32(smem);
    int tid = threadIdx.x, warp = tid >> 5, lane = tid & 31;
    int y = blockIdx.x, x0 = blockIdx.y * 128;
    int wm = (warp >> 1) * 32, wn = (warp & 1) * 32;
    int W = 128 + 2 * d;

    float c[2][4][4];
    #pragma unroll
    for (int mt = 0; mt < 2; mt++)
        #pragma unroll
        for (int nt = 0; nt < 4; nt++)
            #pragma unroll
            for (int r = 0; r < 4; r++) c[mt][nt][r] = 0.f;

    {
        int ysrc = y - d;
        bool yok = (ysrc >= 0 && ysrc < LL);
        int nch = W * 8;
        for (int cid = tid; cid < nch; cid += 256) {
            int row = cid >> 3, c7 = cid & 7;
            int gx = x0 - d + row;
            bool ok = yok && gx >= 0 && gx < LL;
            size_t base = ((size_t)(ok ? ysrc : 0) * LL + (ok ? gx : 0)) * 64;
            int off = row * 128 + ((c7 ^ (row & 7)) * 16);
            int sz = ok ? 16 : 0;
            cpa16(sb + SLAB_H + off, (const char*)(xh + base) + c7 * 16, sz);
            cpa16(sb + SLAB_L + off, (const char*)(xl + base) + c7 * 16, sz);
        }
        cpa_commit();
        const char* bhp = (const char*)wh;
        const char* blp = (const char*)wl;
        #pragma unroll
        for (int k = 0; k < 2; k++) {
            int ch = tid + k * 256;
            int oc = ch >> 3, col16 = ch & 7;
            int off = oc * 128 + ((col16 ^ (oc & 7)) * 16);
            cpa16(sb + BH(0) + off, bhp + ch * 16, 16);
            cpa16(sb + BL(0) + off, blp + ch * 16, 16);
        }
        cpa_commit();
    }

    for (int t = 0; t < 9; t++) {
        int ky = t / 3, kx = t % 3, p = t & 1;
        if (t > 0) {
            __syncthreads();
            if (kx == 0) {
                int ysrc = y + (ky - 1) * d;
                bool yok = (ysrc >= 0 && ysrc < LL);
                int nch = W * 8;
                for (int cid = tid; cid < nch; cid += 256) {
                    int row = cid >> 3, c7 = cid & 7;
                    int gx = x0 - d + row;
                    bool ok = yok && gx >= 0 && gx < LL;
                    size_t base = ((size_t)(ok ? ysrc : 0) * LL + (ok ? gx : 0)) * 64;
                    int off = row * 128 + ((c7 ^ (row & 7)) * 16);
                    int sz = ok ? 16 : 0;
                    cpa16(sb + SLAB_H + off, (const char*)(xh + base) + c7 * 16, sz);
                    cpa16(sb + SLAB_L + off, (const char*)(xl + base) + c7 * 16, sz);
                }
                cpa_commit();
            }
        }
        if (t < 8) {
            int tn = t + 1, pn = tn & 1;
            const char* bhp = (const char*)(wh + (size_t)tn * 4096);
            const char* blp = (const char*)(wl + (size_t)tn * 4096);
            #pragma unroll
            for (int k = 0; k < 2; k++) {
                int ch = tid + k * 256;
                int oc = ch >> 3, col16 = ch & 7;
                int off = oc * 128 + ((col16 ^ (oc & 7)) * 16);
                cpa16(sb + BH(pn) + off, bhp + ch * 16, 16);
                cpa16(sb + BL(pn) + off, blp + ch * 16, 16);
            }
            cpa_commit();
            cpa_wait1();
        } else {
            cpa_wait0();
        }
        __syncthreads();

        int rofs = kx * d;
        #pragma unroll
        for (int kc = 0; kc < 4; kc++) {
            uint32_t ah[2][4], al[2][4], bh[2][4], bl[2][4];
            #pragma unroll
            for (int mt = 0; mt < 2; mt++) {
                int row = wm + mt * 16 + (lane & 15) + rofs;
                int col16 = kc * 2 + (lane >> 4);
                uint32_t addr = sb + row * 128 + ((col16 ^ (row & 7)) * 16);
                ldm_x4(ah[mt], addr + SLAB_H);
                ldm_x4(al[mt], addr + SLAB_L);
            }
            #pragma unroll
            for (int bt = 0; bt < 2; bt++) {
                int row = wn + bt * 16 + (lane & 15);
                int col16 = kc * 2 + (lane >> 4);
                uint32_t addr = sb + row * 128 + ((col16 ^ (row & 7)) * 16);
                ldm_x4(bh[bt], addr + BH(p));
                ldm_x4(bl[bt], addr + BL(p));
            }
            #pragma unroll
            for (int mt = 0; mt < 2; mt++)
                #pragma unroll
                for (int nt = 0; nt < 4; nt++) {
                    uint32_t bfh[2] = { bh[nt >> 1][nt & 1], bh[nt >> 1][(nt & 1) + 2] };
                    uint32_t bfl[2] = { bl[nt >> 1][nt & 1], bl[nt >> 1][(nt & 1) + 2] };
                    mma_bf16(c[mt][nt], ah[mt], bfh);
                    mma_bf16(c[mt][nt], ah[mt], bfl);
                    mma_bf16(c[mt][nt], al[mt], bfh);
                }
        }
    }
    __syncthreads();

    float* cs = (float*)smem;
    #pragma unroll
    for (int mt = 0; mt < 2; mt++)
        #pragma unroll
        for (int nt = 0; nt < 4; nt++) {
            int m = wm + mt * 16 + (lane >> 2);
            int n = wn + nt * 8 + (lane & 3) * 2;
            cs[n * 136 + m]           = c[mt][nt][0];
            cs[(n + 1) * 136 + m]     = c[mt][nt][1];
            cs[n * 136 + m + 8]       = c[mt][nt][2];
            cs[(n + 1) * 136 + m + 8] = c[mt][nt][3];
        }
    __syncthreads();

    if (conf_w) {
        if (tid < 128) {
            float s = conf_b[0];
            #pragma unroll
            for (int cc = 0; cc < 32; cc++) {
                float v = fmaxf(cs[cc * 136 + tid] + bias[cc], 0.f);
                s += v * conf_w[cc];
            }
            out[(size_t)BINS * NPIX + (size_t)y * LL + x0 + tid] = fast_sigmoid(s);
        }
        return;
    }

    int oc = tid >> 2, seg = tid & 3;
    float s = 0.f, q = 0.f;
    if (oc < OC) {
        float bv = bias[oc];
        float* op = out + (size_t)oc * NPIX + (size_t)y * LL + x0 + seg * 32;
        const float* cr = cs + oc * 136 + seg * 32;
        #pragma unroll
        for (int i = 0; i < 8; i++) {
            float4 v = *(const float4*)(cr + i * 4);
            v.x += bv; v.y += bv; v.z += bv; v.w += bv;
            s += v.x + v.y + v.z + v.w;
            q += v.x*v.x + v.y*v.y + v.z*v.z + v.w*v.w;
            if (act) {
                v.x = fmaxf(v.x, 0.f); v.y = fmaxf(v.y, 0.f);
                v.z = fmaxf(v.z, 0.f); v.w = fmaxf(v.w, 0.f);
            }
            *(float4*)(op + i * 4) = v;
        }
    }
    if (stats) {
        s += __shfl_xor_sync(0xffffffffu, s, 1);
        s += __shfl_xor_sync(0xffffffffu, s, 2);
        q += __shfl_xor_sync(0xffffffffu, q, 1);
        q += __shfl_xor_sync(0xffffffffu, q, 2);
        if (seg == 0) { s_sum[oc] = s; s_sq[oc] = q; }
        __syncthreads();
        if (tid < 64) {
            atomicAdd(&g_ssum[tid], (double)s_sum[tid]);
            atomicAdd(&g_ssq[tid],  (double)s_sq[tid]);
        }
    }
}

// ---------------- finalize stats -------------------------------------------------
__global__ void k_finstats() {
    int c = threadIdx.x;
    double mu  = g_ssum[c] / NPIX;
    double var = g_ssq[c] / NPIX - mu*mu;
    g_mean[c] = (float)mu;
    g_rstd[c] = (float)rsqrt(var + 1e-5);
    g_ssum[c] = 0.0; g_ssq[c] = 0.0;
}

// ---------------- norm/elu (+res) + NHWC hi/lo pack (+optional NHWC logits out) ---
__global__ void __launch_bounds__(256)
k_pack_hl(const float* __restrict__ src, const float* __restrict__ res,
          float* __restrict__ outx, __nv_bfloat16* __restrict__ gh,
          __nv_bfloat16* __restrict__ gl, int IC, int do_norm,
          float* __restrict__ outT) {
    __shared__ float s[64][65];
    int tid = threadIdx.x;
    int px0 = blockIdx.x * 64;
    #pragma unroll
    for (int k = 0; k < 16; k++) {
        int idx = k * 256 + tid;
        int c = idx >> 6, px = idx & 63;
        float v = 0.f;
        if (c < IC) {
            v = src[(size_t)c * NPIX + px0 + px];
            if (do_norm) {
                v = (v - g_mean[c]) * g_rstd[c];
                if (res) v += res[(size_t)c * NPIX + px0 + px];
                v = (v > 0.f) ? v : (__expf(v) - 1.f);
            }
            if (outx) outx[(size_t)c * NPIX + px0 + px] = v;
        }
        s[px][c] = v;
    }
    __syncthreads();
    if (outT) {
        float* ob = outT + (size_t)px0 * BINS;
        for (int l = tid; l < 64 * BINS; l += 256) ob[l] = s[l / BINS][l % BINS];
    }
    if (!gh) return;
    #pragma unroll
    for (int k = 0; k < 2; k++) {
        int ch = k * 256 + tid;
        int px = ch >> 3, c0 = (ch & 7) * 8;
        __nv_bfloat16 hh[8], ll[8];
        #pragma unroll
        for (int j = 0; j < 8; j++) {
            float v = s[px][c0 + j];
            hh[j] = __float2bfloat16(v);
            ll[j] = __float2bfloat16(v - __bfloat162float(hh[j]));
        }
        *(uint4*)(gh + ((size_t)(px0 + px)) * 64 + c0) = *(uint4*)hh;
        *(uint4*)(gl + ((size_t)(px0 + px)) * 64 + c0) = *(uint4*)ll;
    }
}

// ---------------- 1x1 input conv ----------------------------------------------------
__global__ void __launch_bounds__(256)
k_conv1x1_in(const float* __restrict__ f, const float* __restrict__ w,
             const float* __restrict__ b, float* __restrict__ out,
             __nv_bfloat16* __restrict__ gh, __nv_bfloat16* __restrict__ gl) {
    __shared__ float sw_[41*64];
    int tid = threadIdx.x;
    for (int idx = tid; idx < 41*64; idx += 256) {
        int ic = idx >> 6, oc = idx & 63;
        sw_[idx] = w[oc*41 + ic];
    }
    __syncthreads();
    int pix = blockIdx.x * 256 + tid;
    float acc[64];
    #pragma unroll
    for (int o = 0; o < 64; o++) acc[o] = b[o];
    const float* fp = f + (size_t)pix * 41;
    for (int ic = 0; ic < 41; ic++) {
        float v = fp[ic];
        #pragma unroll
        for (int o = 0; o < 64; o++) acc[o] += v * sw_[ic*64 + o];
    }
    #pragma unroll
    for (int o = 0; o < 64; o++) out[(size_t)o * NPIX + pix] = acc[o];
    #pragma unroll
    for (int c0 = 0; c0 < 64; c0 += 8) {
        __nv_bfloat16 hh[8], ll[8];
        #pragma unroll
        for (int j = 0; j < 8; j++) {
            float v = acc[c0 + j];
            hh[j] = __float2bfloat16(v);
            ll[j] = __float2bfloat16(v - __bfloat162float(hh[j]));
        }
        *(uint4*)(gh + (size_t)pix * 64 + c0) = *(uint4*)hh;
        *(uint4*)(gl + (size_t)pix * 64 + c0) = *(uint4*)ll;
    }
}

// ---------------- scalar template gate -----------------------------------------------
__global__ void k_gate(const float* __restrict__ td, const float* __restrict__ tq,
                       const float* __restrict__ w1, const float* __restrict__ b1,
                       const float* __restrict__ w2, const float* __restrict__ b2) {
    __shared__ float red[256];
    int t = threadIdx.x;
    float cnt = 0.f;
    for (int i = t; i < NPIX; i += 256) cnt += (td[i] > 0.f) ? 1.f : 0.f;
    red[t] = cnt; __syncthreads();
    for (int st = 128; st > 0; st >>= 1) {
        if (t < st) red[t] += red[t+st];
        __syncthreads();
    }
    if (t == 0) {
        float f0 = red[0] / (float)NPIX, f1 = tq[0], f2 = (float)LL / 512.f;
        float acc = b2[0];
        #pragma unroll
        for (int j = 0; j < 16; j++) {
            float h = f0*w1[j] + f1*w1[16+j] + f2*w1[32+j] + b1[j];
            acc += fmaxf(h, 0.f) * w2[j];
        }
        g_gate = 1.f / (1.f + expf(-acc));
    }
}

// ---------------- anchor projections: block per (k, side), smem tiled -------------------
__global__ void __launch_bounds__(256)
k_proj_anchor(const float* __restrict__ wl, const float* __restrict__ wr,
              const float* __restrict__ wvl, const float* __restrict__ wvr) {
    __shared__ float sx[64][33];
    __shared__ float sw1[64*ADIM], sw2[64*ADIM];
    int k = blockIdx.x, side = blockIdx.y;
    int ak = k * ASTRIDE;
    int tid = threadIdx.x;
    const float* w1 = side ? wr  : wl;
    const float* w2 = side ? wvr : wvl;
    for (int idx = tid; idx < 64*ADIM; idx += 256) { sw1[idx] = w1[idx]; sw2[idx] = w2[idx]; }

    int a = tid & 31, pg = tid >> 5;   // 32 a-lanes × 8 p-groups
    for (int pt = 0; pt < 12; pt++) {
        int p0 = pt * 32;
        __syncthreads();
        for (int idx = tid; idx < 64*32; idx += 256) {
            int c = idx >> 5, pp = idx & 31;
            int pix = side ? (ak*LL + p0 + pp) : ((p0 + pp)*LL + ak);
            sx[c][pp] = g_x[(size_t)c * NPIX + pix];
        }
        __syncthreads();
        #pragma unroll
        for (int sub = 0; sub < 4; sub++) {
            int pp = pg * 4 + sub;
            float s1 = 0.f, s2 = 0.f;
            #pragma unroll
            for (int c = 0; c < 64; c++) {
                float v = sx[c][pp];
                s1 += v * sw1[c*ADIM + a];
                s2 += v * sw2[c*ADIM + a];
            }
            int p = p0 + pp;
            if (side) { int o = (a*NANCH + k)*LL + p;   g_right[o] = s1; g_vright[o] = s2; }
            else      { int o = (p*NANCH + k)*ADIM + a; g_left[o]  = s1; g_vleft[o]  = s2; }
        }
    }
}

// ---------------- fused attention ------------------------------------------------------
__global__ void __launch_bounds__(128)
k_attn(const float* __restrict__ td, const float* __restrict__ wq,
       const float* __restrict__ wo, const float* __restrict__ wg,
       const float* __restrict__ bg,
       __nv_bfloat16* __restrict__ gh, __nv_bfloat16* __restrict__ gl) {
    __shared__ float s_l[NANCH*ADIM], s_vl[NANCH*ADIM], s_tl[NANCH];
    __shared__ float s_wq[64*ADIM], s_wo[ADIM*64], s_wg[64*64], s_bg[64];
    int i = blockIdx.y;
    int tid = threadIdx.x;
    for (int idx = tid; idx < NANCH*ADIM; idx += 128) {
        s_l[idx]  = g_left [i*NANCH*ADIM + idx];
        s_vl[idx] = g_vleft[i*NANCH*ADIM + idx];
    }
    for (int idx = tid; idx < 64*ADIM; idx += 128) s_wq[idx] = wq[idx];
    for (int idx = tid; idx < ADIM*64; idx += 128) s_wo[idx] = wo[idx];
    for (int idx = tid; idx < 64*64;  idx += 128) s_wg[idx] = wg[idx];
    if (tid < 64) s_bg[tid] = bg[tid];
    if (tid < NANCH) s_tl[tid] = td[i*LL + tid*ASTRIDE];
    __syncthreads();

    int j = blockIdx.x*128 + tid;
    int pix = i*LL + j;
    float g = g_gate;
    float tdij = td[pix];
    const float invs = 0.1767766952966369f;

    float qv[ADIM];
    #pragma unroll
    for (int a = 0; a < ADIM; a++) qv[a] = 0.f;
    for (int c = 0; c < 64; c++) {
        float xv = g_x[(size_t)c*NPIX + pix];
        #pragma unroll
        for (int a = 0; a < ADIM; a++) qv[a] += xv * s_wq[c*ADIM + a];
    }

    float m = -3.0e38f, ssum = 0.f;
    float acc[ADIM];
    #pragma unroll
    for (int a = 0; a < ADIM; a++) acc[a] = 0.f;

    #pragma unroll 2
    for (int k = 0; k < NANCH; k++) {
        float s = 0.f;
        #pragma unroll
        for (int a = 0; a < ADIM; a++) {
            s += qv[a] * s_l[k*ADIM + a];
            s += qv[a] * g_right[((size_t)a*NANCH + k)*LL + j];
        }
        float ts   = s_tl[k] + td[k*ASTRIDE*LL + j];
        float bias = -fabsf(ts - tdij) * (1.f/12.f);
        s = s*invs + g*bias;
        float mn   = fmaxf(m, s);
        float corr = __expf(m - mn);
        float wgt  = __expf(s - mn);
        ssum = ssum*corr + wgt;
        #pragma unroll
        for (int a = 0; a < ADIM; a++)
            acc[a] = acc[a]*corr +
                     wgt * (s_vl[k*ADIM + a] + g_vright[((size_t)a*NANCH + k)*LL + j]);
        m = mn;
    }
    float inv = 1.f / ssum;
    #pragma unroll
    for (int a = 0; a < ADIM; a++) acc[a] *= inv;

    float pv[64];
    #pragma unroll
    for (int c = 0; c < 64; c++) pv[c] = g_x[(size_t)c*NPIX + pix];

    __nv_bfloat16 hh[8], llb[8];
    for (int c = 0; c < 64; c++) {
        float o = 0.f;
        #pragma unroll
        for (int a = 0; a < ADIM; a++) o += acc[a] * s_wo[a*64 + c];
        float gp = s_bg[c];
        #pragma unroll
        for (int c2 = 0; c2 < 64; c2++) gp += pv[c2] * s_wg[c2*64 + c];
        float gate = fast_sigmoid(gp);
        float nv = pv[c] + gate * o;
        g_x[(size_t)c*NPIX + pix] = nv;
        int jj = c & 7;
        hh[jj]  = __float2bfloat16(nv);
        llb[jj] = __float2bfloat16(nv - __bfloat162float(hh[jj]));
        if (jj == 7) {
            *(uint4*)(gh + (size_t)pix * 64 + (c - 7)) = *(uint4*)hh;
            *(uint4*)(gl + (size_t)pix * 64 + (c - 7)) = *(uint4*)llb;
        }
    }
}

// ---------------- symmetrize (tiled transpose) --------------------------------------
__global__ void k_sym(const float* __restrict__ in, float* __restrict__ out) {
    __shared__ float s2[32][33];
    int c = blockIdx.z;
    int ti = blockIdx.y * 32, tj = blockIdx.x * 32;
    const float* p = in + (size_t)c * NPIX;
    float* o = out + (size_t)c * NPIX;
    int tx = threadIdx.x, ty = threadIdx.y;
    #pragma unroll
    for (int k = 0; k < 4; k++) {
        int r = ty + k * 8;
        s2[r][tx] = p[(size_t)(tj + r) * LL + ti + tx];
    }
    __syncthreads();
    #pragma unroll
    for (int k = 0; k < 4; k++) {
        int r = ty + k * 8;
        o[(size_t)(ti + r) * LL + tj + tx] =
            0.5f * (p[(size_t)(ti + r) * LL + tj + tx] + s2[tx][r]);
    }
}

// ========================================================================================
extern "C" void kernel_launch(void* const* d_in, const int* in_sizes, int n_in,
                              void* d_out, int out_size) {
    const float* features = (const float*)d_in[0];
    const float* td       = (const float*)d_in[1];
    const float* tq       = (const float*)d_in[2];
    const float* in_w     = (const float*)d_in[3];
    const float* in_b     = (const float*)d_in[4];
    const float* c1w      = (const float*)d_in[5];
    const float* c1b      = (const float*)d_in[6];
    const float* c2w      = (const float*)d_in[7];
    const float* c2b      = (const float*)d_in[8];
    const float* wq       = (const float*)d_in[9];
    const float* wl       = (const float*)d_in[10];
    const float* wr       = (const float*)d_in[11];
    const float* wvl      = (const float*)d_in[12];
    const float* wvr      = (const float*)d_in[13];
    const float* wo       = (const float*)d_in[14];
    const float* wg       = (const float*)d_in[15];
    const float* bg       = (const float*)d_in[16];
    const float* tgw1     = (const float*)d_in[17];
    const float* tgb1     = (const float*)d_in[18];
    const float* tgw2     = (const float*)d_in[19];
    const float* tgb2     = (const float*)d_in[20];
    const float* dist_w   = (const float*)d_in[21];
    const float* dist_b   = (const float*)d_in[22];
    const float* cf_w1    = (const float*)d_in[23];
    const float* cf_b1    = (const float*)d_in[24];
    const float* cf_w2    = (const float*)d_in[25];
    const float* cf_b2    = (const float*)d_in[26];
    const float* cf_w3    = (const float*)d_in[27];
    const float* cf_b3    = (const float*)d_in[28];
    float* out = (float*)d_out;

    cudaFuncSetAttribute(k_tconv, cudaFuncAttributeMaxDynamicSharedMemorySize, SMEM_T);

    float *x, *a, *b;
    __nv_bfloat16 *gh, *gl, *wh, *wlo;
    cudaGetSymbolAddress((void**)&x,   g_x);
    cudaGetSymbolAddress((void**)&a,   g_a);
    cudaGetSymbolAddress((void**)&b,   g_b);
    cudaGetSymbolAddress((void**)&gh,  g_h);
    cudaGetSymbolAddress((void**)&gl,  g_l);
    cudaGetSymbolAddress((void**)&wh,  g_wh);
    cudaGetSymbolAddress((void**)&wlo, g_wl);

    const size_t WSL = (size_t)9*64*64;
    dim3 tg(LL, 3);
    const int dil[6] = {1, 2, 4, 8, 16, 1};
    const float* nof = nullptr;

    k_wsplit<<<dim3(9,6), 256>>>(c1w, 0, 64, 64);
    k_wsplit<<<dim3(9,6), 256>>>(c2w, 6, 64, 64);
    k_conv1x1_in<<<NPIX/256, 256>>>(features, in_w, in_b, x, gh, gl);

    for (int i = 0; i < 6; i++) {
        k_tconv<<<tg, 256, SMEM_T>>>(gh, gl, wh + (size_t)i*WSL, wlo + (size_t)i*WSL,
                                     c1b + i*64, a, 64, dil[i], 0, 1, nof, nof);
        k_finstats<<<1, 64>>>();
        k_pack_hl<<<NPIX/64, 256>>>(a, nof, (float*)nullptr, gh, gl, 64, 1, (float*)nullptr);
        k_tconv<<<tg, 256, SMEM_T>>>(gh, gl, wh + (size_t)(6+i)*WSL, wlo + (size_t)(6+i)*WSL,
                                     c2b + i*64, a, 64, 1, 0, 1, nof, nof);
        k_finstats<<<1, 64>>>();
        bool attn = (i & 1);
        k_pack_hl<<<NPIX/64, 256>>>(a, x, x,
                                    attn ? (__nv_bfloat16*)nullptr : gh,
                                    attn ? (__nv_bfloat16*)nullptr : gl, 64, 1, (float*)nullptr);
        if (attn) {
            if (i == 1) k_gate<<<1, 256>>>(td, tq, tgw1, tgb1, tgw2, tgb2);
            k_proj_anchor<<<dim3(NANCH, 2), 256>>>(wl, wr, wvl, wvr);
            k_attn<<<dim3(3, LL), 128>>>(td, wq, wo, wg, bg, gh, gl);
        }
    }

    // distance head (OC=63) + symmetrize
    k_wsplit<<<dim3(9,1), 256>>>(dist_w, 12, 63, 64);
    k_tconv<<<tg, 256, SMEM_T>>>(gh, gl, wh + (size_t)12*WSL, wlo + (size_t)12*WSL,
                                 dist_b, a, 63, 1, 0, 0, nof, nof);
    k_sym<<<dim3(12, 12, BINS), dim3(32, 8)>>>(a, b);

    // confidence head; the pack also emits the NHWC distance logits to out
    k_wsplit<<<dim3(9,1), 256>>>(cf_w1, 13, 32, 63);
    k_wsplit<<<dim3(9,1), 256>>>(cf_w2, 14, 32, 32);
    k_pack_hl<<<NPIX/64, 256>>>(b, nof, (float*)nullptr, gh, gl, 63, 0, out);
    k_tconv<<<tg, 256, SMEM_T>>>(gh, gl, wh + (size_t)13*WSL, wlo + (size_t)13*WSL,
                                 cf_b1, a, 32, 1, 1, 0, nof, nof);
    k_pack_hl<<<NPIX/64, 256>>>(a, nof, (float*)nullptr, gh, gl, 32, 0, (float*)nullptr);
    k_tconv<<<tg, 256, SMEM_T>>>(gh, gl, wh + (size_t)14*WSL, wlo + (size_t)14*WSL,
                                 cf_b2, out, 32, 1, 1, 0, cf_w3, cf_b3);
}

// round 16
// speedup vs baseline: 1.2731x; 1.2731x over previous
#include <cuda_runtime.h>
#include <cuda_bf16.h>
#include <math.h>
#include <stdint.h>

#define LL    384
#define NPIX  (LL*LL)
#define HID   64
#define BINS  63
#define ADIM  32
#define NANCH 32
#define ASTRIDE 12

// ---------------- scratch ------------------------------------------------------
__device__ float g_x[HID*NPIX];
__device__ float g_a[HID*NPIX];
__device__ float g_b[HID*NPIX];
__device__ __nv_bfloat16 g_h[NPIX*64];
__device__ __nv_bfloat16 g_l[NPIX*64];
__device__ __nv_bfloat16 g_wh[15*9*64*64];
__device__ __nv_bfloat16 g_wl[15*9*64*64];
__device__ float g_left [LL*NANCH*ADIM];
__device__ float g_right[ADIM*NANCH*LL];    // [a][k][p] coalesced for attn
__device__ float g_vleft [LL*NANCH*ADIM];
__device__ float g_vright[ADIM*NANCH*LL];
__device__ float g_mean[HID];
__device__ float g_rstd[HID];
__device__ double g_ssum[HID];
__device__ double g_ssq[HID];
__device__ float g_gate;

// ---------------- helpers ------------------------------------------------------
__device__ __forceinline__ uint32_t smem_u32(const void* p) {
    uint32_t a;
    asm("{ .reg .u64 t; cvta.to.shared.u64 t, %1; cvt.u32.u64 %0, t; }" : "=r"(a) : "l"(p));
    return a;
}
__device__ __forceinline__ void ldm_x4(uint32_t* r, uint32_t addr) {
    asm volatile("ldmatrix.sync.aligned.m8n8.x4.shared.b16 {%0,%1,%2,%3}, [%4];"
        : "=r"(r[0]), "=r"(r[1]), "=r"(r[2]), "=r"(r[3]) : "r"(addr));
}
__device__ __forceinline__ void mma_bf16(float* c, const uint32_t* a, const uint32_t* b) {
    asm volatile(
        "mma.sync.aligned.m16n8k16.row.col.f32.bf16.bf16.f32 "
        "{%0,%1,%2,%3}, {%4,%5,%6,%7}, {%8,%9}, {%0,%1,%2,%3};"
        : "+f"(c[0]), "+f"(c[1]), "+f"(c[2]), "+f"(c[3])
        : "r"(a[0]), "r"(a[1]), "r"(a[2]), "r"(a[3]), "r"(b[0]), "r"(b[1]));
}
__device__ __forceinline__ void cpa16(uint32_t d, const void* s, int sz) {
    asm volatile("cp.async.cg.shared.global [%0], [%1], 16, %2;"
        :: "r"(d), "l"(s), "r"(sz) : "memory");
}
__device__ __forceinline__ void cpa_commit() {
    asm volatile("cp.async.commit_group;" ::: "memory");
}
__device__ __forceinline__ void cpa_wait1() {
    asm volatile("cp.async.wait_group 1;" ::: "memory");
}
__device__ __forceinline__ void cpa_wait0() {
    asm volatile("cp.async.wait_group 0;" ::: "memory");
}
__device__ __forceinline__ float fast_sigmoid(float v) {
    return 1.f / (1.f + __expf(-v));
}

// ---------------- weight split -------------------------------------------------
__global__ void k_wsplit(const float* __restrict__ src, int slot0, int OC, int IC) {
    int t = blockIdx.x, s = blockIdx.y;
    const float* w = src + (size_t)s * OC * IC * 9;
    __nv_bfloat16* dh = g_wh + ((size_t)(slot0 + s) * 9 + t) * 4096;
    __nv_bfloat16* dl = g_wl + ((size_t)(slot0 + s) * 9 + t) * 4096;
    for (int idx = threadIdx.x; idx < 4096; idx += 256) {
        int oc = idx >> 6, ic = idx & 63;
        float v = (oc < OC && ic < IC) ? w[((size_t)oc * IC + ic) * 9 + t] : 0.f;
        __nv_bfloat16 h = __float2bfloat16(v);
        dh[idx] = h;
        dl[idx] = __float2bfloat16(v - __bfloat162float(h));
    }
}

// ---------------- HMMA 3x3 conv, M=128 tile, slab-shared A + dbuf B ----------------
#define SLAB_H 0
#define SLAB_L 20480
#define BH(p) (40960 + (p)*16384)
#define BL(p) (40960 + (p)*16384 + 8192)
#define SMEM_T 73728

__global__ void __launch_bounds__(256, 3)
k_tconv(const __nv_bfloat16* __restrict__ xh, const __nv_bfloat16* __restrict__ xl,
        const __nv_bfloat16* __restrict__ wh, const __nv_bfloat16* __restrict__ wl,
        const float* __restrict__ bias, float* __restrict__ out,
        int OC, int d, int act, int stats,
        const float* __restrict__ conf_w, const float* __restrict__ conf_b) {
    extern __shared__ __align__(16) char smem[];
    __shared__ float s_sum[64], s_sq[64];
    uint32_t sb = smem_u32(smem);
    int tid = threadIdx.x, warp = tid >> 5, lane = tid & 31;
    int y = blockIdx.x, x0 = blockIdx.y * 128;
    int wm = (warp >> 1) * 32, wn = (warp & 1) * 32;
    int W = 128 + 2 * d;

    float c[2][4][4];
    #pragma unroll
    for (int mt = 0; mt < 2; mt++)
        #pragma unroll
        for (int nt = 0; nt < 4; nt++)
            #pragma unroll
            for (int r = 0; r < 4; r++) c[mt][nt][r] = 0.f;

    {
        int ysrc = y - d;
        bool yok = (ysrc >= 0 && ysrc < LL);
        int nch = W * 8;
        for (int cid = tid; cid < nch; cid += 256) {
            int row = cid >> 3, c7 = cid & 7;
            int gx = x0 - d + row;
            bool ok = yok && gx >= 0 && gx < LL;
            size_t base = ((size_t)(ok ? ysrc : 0) * LL + (ok ? gx : 0)) * 64;
            int off = row * 128 + ((c7 ^ (row & 7)) * 16);
            int sz = ok ? 16 : 0;
            cpa16(sb + SLAB_H + off, (const char*)(xh + base) + c7 * 16, sz);
            cpa16(sb + SLAB_L + off, (const char*)(xl + base) + c7 * 16, sz);
        }
        cpa_commit();
        const char* bhp = (const char*)wh;
        const char* blp = (const char*)wl;
        #pragma unroll
        for (int k = 0; k < 2; k++) {
            int ch = tid + k * 256;
            int oc = ch >> 3, col16 = ch & 7;
            int off = oc * 128 + ((col16 ^ (oc & 7)) * 16);
            cpa16(sb + BH(0) + off, bhp + ch * 16, 16);
            cpa16(sb + BL(0) + off, blp + ch * 16, 16);
        }
        cpa_commit();
    }

    for (int t = 0; t < 9; t++) {
        int ky = t / 3, kx = t % 3, p = t & 1;
        if (t > 0) {
            __syncthreads();
            if (kx == 0) {
                int ysrc = y + (ky - 1) * d;
                bool yok = (ysrc >= 0 && ysrc < LL);
                int nch = W * 8;
                for (int cid = tid; cid < nch; cid += 256) {
                    int row = cid >> 3, c7 = cid & 7;
                    int gx = x0 - d + row;
                    bool ok = yok && gx >= 0 && gx < LL;
                    size_t base = ((size_t)(ok ? ysrc : 0) * LL + (ok ? gx : 0)) * 64;
                    int off = row * 128 + ((c7 ^ (row & 7)) * 16);
                    int sz = ok ? 16 : 0;
                    cpa16(sb + SLAB_H + off, (const char*)(xh + base) + c7 * 16, sz);
                    cpa16(sb + SLAB_L + off, (const char*)(xl + base) + c7 * 16, sz);
                }
                cpa_commit();
            }
        }
        if (t < 8) {
            int tn = t + 1, pn = tn & 1;
            const char* bhp = (const char*)(wh + (size_t)tn * 4096);
            const char* blp = (const char*)(wl + (size_t)tn * 4096);
            #pragma unroll
            for (int k = 0; k < 2; k++) {
                int ch = tid + k * 256;
                int oc = ch >> 3, col16 = ch & 7;
                int off = oc * 128 + ((col16 ^ (oc & 7)) * 16);
                cpa16(sb + BH(pn) + off, bhp + ch * 16, 16);
                cpa16(sb + BL(pn) + off, blp + ch * 16, 16);
            }
            cpa_commit();
            cpa_wait1();
        } else {
            cpa_wait0();
        }
        __syncthreads();

        int rofs = kx * d;
        #pragma unroll
        for (int kc = 0; kc < 4; kc++) {
            uint32_t ah[2][4], al[2][4], bh[2][4], bl[2][4];
            #pragma unroll
            for (int mt = 0; mt < 2; mt++) {
                int row = wm + mt * 16 + (lane & 15) + rofs;
                int col16 = kc * 2 + (lane >> 4);
                uint32_t addr = sb + row * 128 + ((col16 ^ (row & 7)) * 16);
                ldm_x4(ah[mt], addr + SLAB_H);
                ldm_x4(al[mt], addr + SLAB_L);
            }
            #pragma unroll
            for (int bt = 0; bt < 2; bt++) {
                int row = wn + bt * 16 + (lane & 15);
                int col16 = kc * 2 + (lane >> 4);
                uint32_t addr = sb + row * 128 + ((col16 ^ (row & 7)) * 16);
                ldm_x4(bh[bt], addr + BH(p));
                ldm_x4(bl[bt], addr + BL(p));
            }
            #pragma unroll
            for (int mt = 0; mt < 2; mt++)
                #pragma unroll
                for (int nt = 0; nt < 4; nt++) {
                    uint32_t bfh[2] = { bh[nt >> 1][nt & 1], bh[nt >> 1][(nt & 1) + 2] };
                    uint32_t bfl[2] = { bl[nt >> 1][nt & 1], bl[nt >> 1][(nt & 1) + 2] };
                    mma_bf16(c[mt][nt], ah[mt], bfh);
                    mma_bf16(c[mt][nt], ah[mt], bfl);
                    mma_bf16(c[mt][nt], al[mt], bfh);
                }
        }
    }
    __syncthreads();

    float* cs = (float*)smem;
    #pragma unroll
    for (int mt = 0; mt < 2; mt++)
        #pragma unroll
        for (int nt = 0; nt < 4; nt++) {
            int m = wm + mt * 16 + (lane >> 2);
            int n = wn + nt * 8 + (lane & 3) * 2;
            cs[n * 136 + m]           = c[mt][nt][0];
            cs[(n + 1) * 136 + m]     = c[mt][nt][1];
            cs[n * 136 + m + 8]       = c[mt][nt][2];
            cs[(n + 1) * 136 + m + 8] = c[mt][nt][3];
        }
    __syncthreads();

    if (conf_w) {
        if (tid < 128) {
            float s = conf_b[0];
            #pragma unroll
            for (int cc = 0; cc < 32; cc++) {
                float v = fmaxf(cs[cc * 136 + tid] + bias[cc], 0.f);
                s += v * conf_w[cc];
            }
            out[(size_t)BINS * NPIX + (size_t)y * LL + x0 + tid] = fast_sigmoid(s);
        }
        return;
    }

    int oc = tid >> 2, seg = tid & 3;
    float s = 0.f, q = 0.f;
    if (oc < OC) {
        float bv = bias[oc];
        float* op = out + (size_t)oc * NPIX + (size_t)y * LL + x0 + seg * 32;
        const float* cr = cs + oc * 136 + seg * 32;
        #pragma unroll
        for (int i = 0; i < 8; i++) {
            float4 v = *(const float4*)(cr + i * 4);
            v.x += bv; v.y += bv; v.z += bv; v.w += bv;
            s += v.x + v.y + v.z + v.w;
            q += v.x*v.x + v.y*v.y + v.z*v.z + v.w*v.w;
            if (act) {
                v.x = fmaxf(v.x, 0.f); v.y = fmaxf(v.y, 0.f);
                v.z = fmaxf(v.z, 0.f); v.w = fmaxf(v.w, 0.f);
            }
            *(float4*)(op + i * 4) = v;
        }
    }
    if (stats) {
        s += __shfl_xor_sync(0xffffffffu, s, 1);
        s += __shfl_xor_sync(0xffffffffu, s, 2);
        q += __shfl_xor_sync(0xffffffffu, q, 1);
        q += __shfl_xor_sync(0xffffffffu, q, 2);
        if (seg == 0) { s_sum[oc] = s; s_sq[oc] = q; }
        __syncthreads();
        if (tid < 64) {
            atomicAdd(&g_ssum[tid], (double)s_sum[tid]);
            atomicAdd(&g_ssq[tid],  (double)s_sq[tid]);
        }
    }
}

// ---------------- finalize stats -------------------------------------------------
__global__ void k_finstats() {
    int c = threadIdx.x;
    double mu  = g_ssum[c] / NPIX;
    double var = g_ssq[c] / NPIX - mu*mu;
    g_mean[c] = (float)mu;
    g_rstd[c] = (float)rsqrt(var + 1e-5);
    g_ssum[c] = 0.0; g_ssq[c] = 0.0;
}

// ---------------- norm/elu (+res) + NHWC hi/lo pack (+optional NHWC logits out) ---
__global__ void __launch_bounds__(256)
k_pack_hl(const float* __restrict__ src, const float* __restrict__ res,
          float* __restrict__ outx, __nv_bfloat16* __restrict__ gh,
          __nv_bfloat16* __restrict__ gl, int IC, int do_norm,
          float* __restrict__ outT) {
    __shared__ float s[64][65];
    int tid = threadIdx.x;
    int px0 = blockIdx.x * 64;
    #pragma unroll
    for (int k = 0; k < 16; k++) {
        int idx = k * 256 + tid;
        int c = idx >> 6, px = idx & 63;
        float v = 0.f;
        if (c < IC) {
            v = src[(size_t)c * NPIX + px0 + px];
            if (do_norm) {
                v = (v - g_mean[c]) * g_rstd[c];
                if (res) v += res[(size_t)c * NPIX + px0 + px];
                v = (v > 0.f) ? v : (__expf(v) - 1.f);
            }
            if (outx) outx[(size_t)c * NPIX + px0 + px] = v;
        }
        s[px][c] = v;
    }
    __syncthreads();
    if (outT) {
        float* ob = outT + (size_t)px0 * BINS;
        for (int l = tid; l < 64 * BINS; l += 256) ob[l] = s[l / BINS][l % BINS];
    }
    if (!gh) return;
    #pragma unroll
    for (int k = 0; k < 2; k++) {
        int ch = k * 256 + tid;
        int px = ch >> 3, c0 = (ch & 7) * 8;
        __nv_bfloat16 hh[8], ll[8];
        #pragma unroll
        for (int j = 0; j < 8; j++) {
            float v = s[px][c0 + j];
            hh[j] = __float2bfloat16(v);
            ll[j] = __float2bfloat16(v - __bfloat162float(hh[j]));
        }
        *(uint4*)(gh + ((size_t)(px0 + px)) * 64 + c0) = *(uint4*)hh;
        *(uint4*)(gl + ((size_t)(px0 + px)) * 64 + c0) = *(uint4*)ll;
    }
}

// ---------------- 1x1 input conv ----------------------------------------------------
__global__ void __launch_bounds__(256)
k_conv1x1_in(const float* __restrict__ f, const float* __restrict__ w,
             const float* __restrict__ b, float* __restrict__ out,
             __nv_bfloat16* __restrict__ gh, __nv_bfloat16* __restrict__ gl) {
    __shared__ float sw_[41*64];
    int tid = threadIdx.x;
    for (int idx = tid; idx < 41*64; idx += 256) {
        int ic = idx >> 6, oc = idx & 63;
        sw_[idx] = w[oc*41 + ic];
    }
    __syncthreads();
    int pix = blockIdx.x * 256 + tid;
    float acc[64];
    #pragma unroll
    for (int o = 0; o < 64; o++) acc[o] = b[o];
    const float* fp = f + (size_t)pix * 41;
    for (int ic = 0; ic < 41; ic++) {
        float v = fp[ic];
        #pragma unroll
        for (int o = 0; o < 64; o++) acc[o] += v * sw_[ic*64 + o];
    }
    #pragma unroll
    for (int o = 0; o < 64; o++) out[(size_t)o * NPIX + pix] = acc[o];
    #pragma unroll
    for (int c0 = 0; c0 < 64; c0 += 8) {
        __nv_bfloat16 hh[8], ll[8];
        #pragma unroll
        for (int j = 0; j < 8; j++) {
            float v = acc[c0 + j];
            hh[j] = __float2bfloat16(v);
            ll[j] = __float2bfloat16(v - __bfloat162float(hh[j]));
        }
        *(uint4*)(gh + (size_t)pix * 64 + c0) = *(uint4*)hh;
        *(uint4*)(gl + (size_t)pix * 64 + c0) = *(uint4*)ll;
    }
}

// ---------------- scalar template gate -----------------------------------------------
__global__ void k_gate(const float* __restrict__ td, const float* __restrict__ tq,
                       const float* __restrict__ w1, const float* __restrict__ b1,
                       const float* __restrict__ w2, const float* __restrict__ b2) {
    __shared__ float red[256];
    int t = threadIdx.x;
    float cnt = 0.f;
    for (int i = t; i < NPIX; i += 256) cnt += (td[i] > 0.f) ? 1.f : 0.f;
    red[t] = cnt; __syncthreads();
    for (int st = 128; st > 0; st >>= 1) {
        if (t < st) red[t] += red[t+st];
        __syncthreads();
    }
    if (t == 0) {
        float f0 = red[0] / (float)NPIX, f1 = tq[0], f2 = (float)LL / 512.f;
        float acc = b2[0];
        #pragma unroll
        for (int j = 0; j < 16; j++) {
            float h = f0*w1[j] + f1*w1[16+j] + f2*w1[32+j] + b1[j];
            acc += fmaxf(h, 0.f) * w2[j];
        }
        g_gate = 1.f / (1.f + expf(-acc));
    }
}

// ---------------- anchor projections (R14 champion version) ----------------------------
__global__ void k_proj_anchor(const float* __restrict__ wl, const float* __restrict__ wr,
                              const float* __restrict__ wvl, const float* __restrict__ wvr) {
    __shared__ float sx[64];
    int p = blockIdx.x, k = blockIdx.y, side = blockIdx.z;
    int ak = k * ASTRIDE;
    int t = threadIdx.x;
    int pix = side == 0 ? p*LL + ak : ak*LL + p;
    sx[t] = g_x[(size_t)t*NPIX + pix];
    __syncthreads();
    if (t < ADIM) {
        const float* w1 = side ? wr  : wl;
        const float* w2 = side ? wvr : wvl;
        float s1 = 0.f, s2 = 0.f;
        #pragma unroll
        for (int c = 0; c < 64; c++) {
            float v = sx[c];
            s1 += v * w1[c*ADIM + t];
            s2 += v * w2[c*ADIM + t];
        }
        if (side) { int o = (t*NANCH + k)*LL + p;   g_right[o] = s1; g_vright[o] = s2; }
        else      { int o = (p*NANCH + k)*ADIM + t; g_left[o]  = s1; g_vleft[o]  = s2; }
    }
}

// ---------------- fused attention (single g_x read) --------------------------------------
__global__ void __launch_bounds__(128)
k_attn(const float* __restrict__ td, const float* __restrict__ wq,
       const float* __restrict__ wo, const float* __restrict__ wg,
       const float* __restrict__ bg,
       __nv_bfloat16* __restrict__ gh, __nv_bfloat16* __restrict__ gl) {
    __shared__ float s_l[NANCH*ADIM], s_vl[NANCH*ADIM], s_tl[NANCH];
    __shared__ float s_wq[64*ADIM], s_wo[ADIM*64], s_wg[64*64], s_bg[64];
    int i = blockIdx.y;
    int tid = threadIdx.x;
    for (int idx = tid; idx < NANCH*ADIM; idx += 128) {
        s_l[idx]  = g_left [i*NANCH*ADIM + idx];
        s_vl[idx] = g_vleft[i*NANCH*ADIM + idx];
    }
    for (int idx = tid; idx < 64*ADIM; idx += 128) s_wq[idx] = wq[idx];
    for (int idx = tid; idx < ADIM*64; idx += 128) s_wo[idx] = wo[idx];
    for (int idx = tid; idx < 64*64;  idx += 128) s_wg[idx] = wg[idx];
    if (tid < 64) s_bg[tid] = bg[tid];
    if (tid < NANCH) s_tl[tid] = td[i*LL + tid*ASTRIDE];
    __syncthreads();

    int j = blockIdx.x*128 + tid;
    int pix = i*LL + j;
    float g = g_gate;
    float tdij = td[pix];
    const float invs = 0.1767766952966369f;

    // single pass over x: keep pv in registers, derive qv from it
    float pv[64];
    #pragma unroll
    for (int c = 0; c < 64; c++) pv[c] = g_x[(size_t)c*NPIX + pix];

    float qv[ADIM];
    #pragma unroll
    for (int a = 0; a < ADIM; a++) qv[a] = 0.f;
    #pragma unroll 8
    for (int c = 0; c < 64; c++) {
        float xv = pv[c];
        #pragma unroll
        for (int a = 0; a < ADIM; a++) qv[a] += xv * s_wq[c*ADIM + a];
    }

    float m = -3.0e38f, ssum = 0.f;
    float acc[ADIM];
    #pragma unroll
    for (int a = 0; a < ADIM; a++) acc[a] = 0.f;

    #pragma unroll 2
    for (int k = 0; k < NANCH; k++) {
        float s = 0.f;
        #pragma unroll
        for (int a = 0; a < ADIM; a++) {
            s += qv[a] * s_l[k*ADIM + a];
            s += qv[a] * g_right[((size_t)a*NANCH + k)*LL + j];
        }
        float ts   = s_tl[k] + td[k*ASTRIDE*LL + j];
        float bias = -fabsf(ts - tdij) * (1.f/12.f);
        s = s*invs + g*bias;
        float mn   = fmaxf(m, s);
        float corr = __expf(m - mn);
        float wgt  = __expf(s - mn);
        ssum = ssum*corr + wgt;
        #pragma unroll
        for (int a = 0; a < ADIM; a++)
            acc[a] = acc[a]*corr +
                     wgt * (s_vl[k*ADIM + a] + g_vright[((size_t)a*NANCH + k)*LL + j]);
        m = mn;
    }
    float inv = 1.f / ssum;
    #pragma unroll
    for (int a = 0; a < ADIM; a++) acc[a] *= inv;

    __nv_bfloat16 hh[8], llb[8];
    for (int c = 0; c < 64; c++) {
        float o = 0.f;
        #pragma unroll
        for (int a = 0; a < ADIM; a++) o += acc[a] * s_wo[a*64 + c];
        float gp = s_bg[c];
        #pragma unroll
        for (int c2 = 0; c2 < 64; c2++) gp += pv[c2] * s_wg[c2*64 + c];
        float gate = fast_sigmoid(gp);
        float nv = pv[c] + gate * o;
        g_x[(size_t)c*NPIX + pix] = nv;
        int jj = c & 7;
        hh[jj]  = __float2bfloat16(nv);
        llb[jj] = __float2bfloat16(nv - __bfloat162float(hh[jj]));
        if (jj == 7) {
            *(uint4*)(gh + (size_t)pix * 64 + (c - 7)) = *(uint4*)hh;
            *(uint4*)(gl + (size_t)pix * 64 + (c - 7)) = *(uint4*)llb;
        }
    }
}

// ---------------- symmetrize (tiled transpose) --------------------------------------
__global__ void k_sym(const float* __restrict__ in, float* __restrict__ out) {
    __shared__ float s2[32][33];
    int c = blockIdx.z;
    int ti = blockIdx.y * 32, tj = blockIdx.x * 32;
    const float* p = in + (size_t)c * NPIX;
    float* o = out + (size_t)c * NPIX;
    int tx = threadIdx.x, ty = threadIdx.y;
    #pragma unroll
    for (int k = 0; k < 4; k++) {
        int r = ty + k * 8;
        s2[r][tx] = p[(size_t)(tj + r) * LL + ti + tx];
    }
    __syncthreads();
    #pragma unroll
    for (int k = 0; k < 4; k++) {
        int r = ty + k * 8;
        o[(size_t)(ti + r) * LL + tj + tx] =
            0.5f * (p[(size_t)(ti + r) * LL + tj + tx] + s2[tx][r]);
    }
}

// ========================================================================================
extern "C" void kernel_launch(void* const* d_in, const int* in_sizes, int n_in,
                              void* d_out, int out_size) {
    const float* features = (const float*)d_in[0];
    const float* td       = (const float*)d_in[1];
    const float* tq       = (const float*)d_in[2];
    const float* in_w     = (const float*)d_in[3];
    const float* in_b     = (const float*)d_in[4];
    const float* c1w      = (const float*)d_in[5];
    const float* c1b      = (const float*)d_in[6];
    const float* c2w      = (const float*)d_in[7];
    const float* c2b      = (const float*)d_in[8];
    const float* wq       = (const float*)d_in[9];
    const float* wl       = (const float*)d_in[10];
    const float* wr       = (const float*)d_in[11];
    const float* wvl      = (const float*)d_in[12];
    const float* wvr      = (const float*)d_in[13];
    const float* wo       = (const float*)d_in[14];
    const float* wg       = (const float*)d_in[15];
    const float* bg       = (const float*)d_in[16];
    const float* tgw1     = (const float*)d_in[17];
    const float* tgb1     = (const float*)d_in[18];
    const float* tgw2     = (const float*)d_in[19];
    const float* tgb2     = (const float*)d_in[20];
    const float* dist_w   = (const float*)d_in[21];
    const float* dist_b   = (const float*)d_in[22];
    const float* cf_w1    = (const float*)d_in[23];
    const float* cf_b1    = (const float*)d_in[24];
    const float* cf_w2    = (const float*)d_in[25];
    const float* cf_b2    = (const float*)d_in[26];
    const float* cf_w3    = (const float*)d_in[27];
    const float* cf_b3    = (const float*)d_in[28];
    float* out = (float*)d_out;

    cudaFuncSetAttribute(k_tconv, cudaFuncAttributeMaxDynamicSharedMemorySize, SMEM_T);

    float *x, *a, *b;
    __nv_bfloat16 *gh, *gl, *wh, *wlo;
    cudaGetSymbolAddress((void**)&x,   g_x);
    cudaGetSymbolAddress((void**)&a,   g_a);
    cudaGetSymbolAddress((void**)&b,   g_b);
    cudaGetSymbolAddress((void**)&gh,  g_h);
    cudaGetSymbolAddress((void**)&gl,  g_l);
    cudaGetSymbolAddress((void**)&wh,  g_wh);
    cudaGetSymbolAddress((void**)&wlo, g_wl);

    const size_t WSL = (size_t)9*64*64;
    dim3 tg(LL, 3);
    const int dil[6] = {1, 2, 4, 8, 16, 1};
    const float* nof = nullptr;

    k_wsplit<<<dim3(9,6), 256>>>(c1w, 0, 64, 64);
    k_wsplit<<<dim3(9,6), 256>>>(c2w, 6, 64, 64);
    k_conv1x1_in<<<NPIX/256, 256>>>(features, in_w, in_b, x, gh, gl);

    for (int i = 0; i < 6; i++) {
        k_tconv<<<tg, 256, SMEM_T>>>(gh, gl, wh + (size_t)i*WSL, wlo + (size_t)i*WSL,
                                     c1b + i*64, a, 64, dil[i], 0, 1, nof, nof);
        k_finstats<<<1, 64>>>();
        k_pack_hl<<<NPIX/64, 256>>>(a, nof, (float*)nullptr, gh, gl, 64, 1, (float*)nullptr);
        k_tconv<<<tg, 256, SMEM_T>>>(gh, gl, wh + (size_t)(6+i)*WSL, wlo + (size_t)(6+i)*WSL,
                                     c2b + i*64, a, 64, 1, 0, 1, nof, nof);
        k_finstats<<<1, 64>>>();
        bool attn = (i & 1);
        k_pack_hl<<<NPIX/64, 256>>>(a, x, x,
                                    attn ? (__nv_bfloat16*)nullptr : gh,
                                    attn ? (__nv_bfloat16*)nullptr : gl, 64, 1, (float*)nullptr);
        if (attn) {
            if (i == 1) k_gate<<<1, 256>>>(td, tq, tgw1, tgb1, tgw2, tgb2);
            k_proj_anchor<<<dim3(LL, NANCH, 2), 64>>>(wl, wr, wvl, wvr);
            k_attn<<<dim3(3, LL), 128>>>(td, wq, wo, wg, bg, gh, gl);
        }
    }

    // distance head (OC=63) + symmetrize
    k_wsplit<<<dim3(9,1), 256>>>(dist_w, 12, 63, 64);
    k_tconv<<<tg, 256, SMEM_T>>>(gh, gl, wh + (size_t)12*WSL, wlo + (size_t)12*WSL,
                                 dist_b, a, 63, 1, 0, 0, nof, nof);
    k_sym<<<dim3(12, 12, BINS), dim3(32, 8)>>>(a, b);

    // confidence head; the pack also emits the NHWC distance logits to out
    k_wsplit<<<dim3(9,1), 256>>>(cf_w1, 13, 32, 63);
    k_wsplit<<<dim3(9,1), 256>>>(cf_w2, 14, 32, 32);
    k_pack_hl<<<NPIX/64, 256>>>(b, nof, (float*)nullptr, gh, gl, 63, 0, out);
    k_tconv<<<tg, 256, SMEM_T>>>(gh, gl, wh + (size_t)13*WSL, wlo + (size_t)13*WSL,
                                 cf_b1, a, 32, 1, 1, 0, nof, nof);
    k_pack_hl<<<NPIX/64, 256>>>(a, nof, (float*)nullptr, gh, gl, 32, 0, (float*)nullptr);
    k_tconv<<<tg, 256, SMEM_T>>>(gh, gl, wh + (size_t)14*WSL, wlo + (size_t)14*WSL,
                                 cf_b2, out, 32, 1, 1, 0, cf_w3, cf_b3);
}

// round 17
// speedup vs baseline: 1.3561x; 1.0652x over previous
#include <cuda_runtime.h>
#include <cuda_bf16.h>
#include <math.h>
#include <stdint.h>

#define LL    384
#define NPIX  (LL*LL)
#define HID   64
#define BINS  63
#define ADIM  32
#define NANCH 32
#define ASTRIDE 12

// ---------------- scratch ------------------------------------------------------
__device__ float g_x[HID*NPIX];
__device__ float g_a[HID*NPIX];
__device__ float g_b[HID*NPIX];
__device__ __nv_bfloat16 g_h[NPIX*64];
__device__ __nv_bfloat16 g_l[NPIX*64];
__device__ __nv_bfloat16 g_wh[15*9*64*64];
__device__ __nv_bfloat16 g_wl[15*9*64*64];
__device__ float g_left [LL*NANCH*ADIM];
__device__ float g_right[ADIM*NANCH*LL];    // [a][k][p] coalesced for attn
__device__ float g_vleft [LL*NANCH*ADIM];
__device__ float g_vright[ADIM*NANCH*LL];
__device__ float g_mean[HID];
__device__ float g_rstd[HID];
__device__ double g_ssum[HID];
__device__ double g_ssq[HID];
__device__ float g_gate;

// ---------------- helpers ------------------------------------------------------
__device__ __forceinline__ uint32_t smem_u32(const void* p) {
    uint32_t a;
    asm("{ .reg .u64 t; cvta.to.shared.u64 t, %1; cvt.u32.u64 %0, t; }" : "=r"(a) : "l"(p));
    return a;
}
__device__ __forceinline__ void ldm_x4(uint32_t* r, uint32_t addr) {
    asm volatile("ldmatrix.sync.aligned.m8n8.x4.shared.b16 {%0,%1,%2,%3}, [%4];"
        : "=r"(r[0]), "=r"(r[1]), "=r"(r[2]), "=r"(r[3]) : "r"(addr));
}
__device__ __forceinline__ void mma_bf16(float* c, const uint32_t* a, const uint32_t* b) {
    asm volatile(
        "mma.sync.aligned.m16n8k16.row.col.f32.bf16.bf16.f32 "
        "{%0,%1,%2,%3}, {%4,%5,%6,%7}, {%8,%9}, {%0,%1,%2,%3};"
        : "+f"(c[0]), "+f"(c[1]), "+f"(c[2]), "+f"(c[3])
        : "r"(a[0]), "r"(a[1]), "r"(a[2]), "r"(a[3]), "r"(b[0]), "r"(b[1]));
}
__device__ __forceinline__ void cpa16(uint32_t d, const void* s, int sz) {
    asm volatile("cp.async.cg.shared.global [%0], [%1], 16, %2;"
        :: "r"(d), "l"(s), "r"(sz) : "memory");
}
__device__ __forceinline__ void cpa_commit() {
    asm volatile("cp.async.commit_group;" ::: "memory");
}
__device__ __forceinline__ void cpa_wait1() {
    asm volatile("cp.async.wait_group 1;" ::: "memory");
}
__device__ __forceinline__ void cpa_wait0() {
    asm volatile("cp.async.wait_group 0;" ::: "memory");
}
__device__ __forceinline__ float fast_sigmoid(float v) {
    return 1.f / (1.f + __expf(-v));
}

// ---------------- weight split -------------------------------------------------
__global__ void k_wsplit(const float* __restrict__ src, int slot0, int OC, int IC) {
    int t = blockIdx.x, s = blockIdx.y;
    const float* w = src + (size_t)s * OC * IC * 9;
    __nv_bfloat16* dh = g_wh + ((size_t)(slot0 + s) * 9 + t) * 4096;
    __nv_bfloat16* dl = g_wl + ((size_t)(slot0 + s) * 9 + t) * 4096;
    for (int idx = threadIdx.x; idx < 4096; idx += 256) {
        int oc = idx >> 6, ic = idx & 63;
        float v = (oc < OC && ic < IC) ? w[((size_t)oc * IC + ic) * 9 + t] : 0.f;
        __nv_bfloat16 h = __float2bfloat16(v);
        dh[idx] = h;
        dl[idx] = __float2bfloat16(v - __bfloat162float(h));
    }
}

// ---------------- HMMA 3x3 conv, M=128 tile, slab-shared A + dbuf B ----------------
#define SLAB_H 0
#define SLAB_L 20480
#define BH(p) (40960 + (p)*16384)
#define BL(p) (40960 + (p)*16384 + 8192)
#define SMEM_T 73728

__global__ void __launch_bounds__(256, 3)
k_tconv(const __nv_bfloat16* __restrict__ xh, const __nv_bfloat16* __restrict__ xl,
        const __nv_bfloat16* __restrict__ wh, const __nv_bfloat16* __restrict__ wl,
        const float* __restrict__ bias, float* __restrict__ out,
        int OC, int d, int act, int stats,
        const float* __restrict__ conf_w, const float* __restrict__ conf_b) {
    extern __shared__ __align__(16) char smem[];
    __shared__ float s_sum[64], s_sq[64];
    uint32_t sb = smem_u32(smem);
    int tid = threadIdx.x, warp = tid >> 5, lane = tid & 31;
    int y = blockIdx.x, x0 = blockIdx.y * 128;
    int wm = (warp >> 1) * 32, wn = (warp & 1) * 32;
    int W = 128 + 2 * d;

    float c[2][4][4];
    #pragma unroll
    for (int mt = 0; mt < 2; mt++)
        #pragma unroll
        for (int nt = 0; nt < 4; nt++)
            #pragma unroll
            for (int r = 0; r < 4; r++) c[mt][nt][r] = 0.f;

    {
        int ysrc = y - d;
        bool yok = (ysrc >= 0 && ysrc < LL);
        int nch = W * 8;
        for (int cid = tid; cid < nch; cid += 256) {
            int row = cid >> 3, c7 = cid & 7;
            int gx = x0 - d + row;
            bool ok = yok && gx >= 0 && gx < LL;
            size_t base = ((size_t)(ok ? ysrc : 0) * LL + (ok ? gx : 0)) * 64;
            int off = row * 128 + ((c7 ^ (row & 7)) * 16);
            int sz = ok ? 16 : 0;
            cpa16(sb + SLAB_H + off, (const char*)(xh + base) + c7 * 16, sz);
            cpa16(sb + SLAB_L + off, (const char*)(xl + base) + c7 * 16, sz);
        }
        cpa_commit();
        const char* bhp = (const char*)wh;
        const char* blp = (const char*)wl;
        #pragma unroll
        for (int k = 0; k < 2; k++) {
            int ch = tid + k * 256;
            int oc = ch >> 3, col16 = ch & 7;
            int off = oc * 128 + ((col16 ^ (oc & 7)) * 16);
            cpa16(sb + BH(0) + off, bhp + ch * 16, 16);
            cpa16(sb + BL(0) + off, blp + ch * 16, 16);
        }
        cpa_commit();
    }

    for (int t = 0; t < 9; t++) {
        int ky = t / 3, kx = t % 3, p = t & 1;
        if (t > 0) {
            __syncthreads();
            if (kx == 0) {
                int ysrc = y + (ky - 1) * d;
                bool yok = (ysrc >= 0 && ysrc < LL);
                int nch = W * 8;
                for (int cid = tid; cid < nch; cid += 256) {
                    int row = cid >> 3, c7 = cid & 7;
                    int gx = x0 - d + row;
                    bool ok = yok && gx >= 0 && gx < LL;
                    size_t base = ((size_t)(ok ? ysrc : 0) * LL + (ok ? gx : 0)) * 64;
                    int off = row * 128 + ((c7 ^ (row & 7)) * 16);
                    int sz = ok ? 16 : 0;
                    cpa16(sb + SLAB_H + off, (const char*)(xh + base) + c7 * 16, sz);
                    cpa16(sb + SLAB_L + off, (const char*)(xl + base) + c7 * 16, sz);
                }
                cpa_commit();
            }
        }
        if (t < 8) {
            int tn = t + 1, pn = tn & 1;
            const char* bhp = (const char*)(wh + (size_t)tn * 4096);
            const char* blp = (const char*)(wl + (size_t)tn * 4096);
            #pragma unroll
            for (int k = 0; k < 2; k++) {
                int ch = tid + k * 256;
                int oc = ch >> 3, col16 = ch & 7;
                int off = oc * 128 + ((col16 ^ (oc & 7)) * 16);
                cpa16(sb + BH(pn) + off, bhp + ch * 16, 16);
                cpa16(sb + BL(pn) + off, blp + ch * 16, 16);
            }
            cpa_commit();
            cpa_wait1();
        } else {
            cpa_wait0();
        }
        __syncthreads();

        int rofs = kx * d;
        #pragma unroll
        for (int kc = 0; kc < 4; kc++) {
            uint32_t ah[2][4], al[2][4], bh[2][4], bl[2][4];
            #pragma unroll
            for (int mt = 0; mt < 2; mt++) {
                int row = wm + mt * 16 + (lane & 15) + rofs;
                int col16 = kc * 2 + (lane >> 4);
                uint32_t addr = sb + row * 128 + ((col16 ^ (row & 7)) * 16);
                ldm_x4(ah[mt], addr + SLAB_H);
                ldm_x4(al[mt], addr + SLAB_L);
            }
            #pragma unroll
            for (int bt = 0; bt < 2; bt++) {
                int row = wn + bt * 16 + (lane & 15);
                int col16 = kc * 2 + (lane >> 4);
                uint32_t addr = sb + row * 128 + ((col16 ^ (row & 7)) * 16);
                ldm_x4(bh[bt], addr + BH(p));
                ldm_x4(bl[bt], addr + BL(p));
            }
            #pragma unroll
            for (int mt = 0; mt < 2; mt++)
                #pragma unroll
                for (int nt = 0; nt < 4; nt++) {
                    uint32_t bfh[2] = { bh[nt >> 1][nt & 1], bh[nt >> 1][(nt & 1) + 2] };
                    uint32_t bfl[2] = { bl[nt >> 1][nt & 1], bl[nt >> 1][(nt & 1) + 2] };
                    mma_bf16(c[mt][nt], ah[mt], bfh);
                    mma_bf16(c[mt][nt], ah[mt], bfl);
                    mma_bf16(c[mt][nt], al[mt], bfh);
                }
        }
    }
    __syncthreads();

    float* cs = (float*)smem;
    #pragma unroll
    for (int mt = 0; mt < 2; mt++)
        #pragma unroll
        for (int nt = 0; nt < 4; nt++) {
            int m = wm + mt * 16 + (lane >> 2);
            int n = wn + nt * 8 + (lane & 3) * 2;
            cs[n * 136 + m]           = c[mt][nt][0];
            cs[(n + 1) * 136 + m]     = c[mt][nt][1];
            cs[n * 136 + m + 8]       = c[mt][nt][2];
            cs[(n + 1) * 136 + m + 8] = c[mt][nt][3];
        }
    __syncthreads();

    if (conf_w) {
        if (tid < 128) {
            float s = conf_b[0];
            #pragma unroll
            for (int cc = 0; cc < 32; cc++) {
                float v = fmaxf(cs[cc * 136 + tid] + bias[cc], 0.f);
                s += v * conf_w[cc];
            }
            out[(size_t)BINS * NPIX + (size_t)y * LL + x0 + tid] = fast_sigmoid(s);
        }
        return;
    }

    int oc = tid >> 2, seg = tid & 3;
    float s = 0.f, q = 0.f;
    if (oc < OC) {
        float bv = bias[oc];
        float* op = out + (size_t)oc * NPIX + (size_t)y * LL + x0 + seg * 32;
        const float* cr = cs + oc * 136 + seg * 32;
        #pragma unroll
        for (int i = 0; i < 8; i++) {
            float4 v = *(const float4*)(cr + i * 4);
            v.x += bv; v.y += bv; v.z += bv; v.w += bv;
            s += v.x + v.y + v.z + v.w;
            q += v.x*v.x + v.y*v.y + v.z*v.z + v.w*v.w;
            if (act) {
                v.x = fmaxf(v.x, 0.f); v.y = fmaxf(v.y, 0.f);
                v.z = fmaxf(v.z, 0.f); v.w = fmaxf(v.w, 0.f);
            }
            *(float4*)(op + i * 4) = v;
        }
    }
    if (stats) {
        s += __shfl_xor_sync(0xffffffffu, s, 1);
        s += __shfl_xor_sync(0xffffffffu, s, 2);
        q += __shfl_xor_sync(0xffffffffu, q, 1);
        q += __shfl_xor_sync(0xffffffffu, q, 2);
        if (seg == 0) { s_sum[oc] = s; s_sq[oc] = q; }
        __syncthreads();
        if (tid < 64) {
            atomicAdd(&g_ssum[tid], (double)s_sum[tid]);
            atomicAdd(&g_ssq[tid],  (double)s_sq[tid]);
        }
    }
}

// ---------------- finalize stats -------------------------------------------------
__global__ void k_finstats() {
    int c = threadIdx.x;
    double mu  = g_ssum[c] / NPIX;
    double var = g_ssq[c] / NPIX - mu*mu;
    g_mean[c] = (float)mu;
    g_rstd[c] = (float)rsqrt(var + 1e-5);
    g_ssum[c] = 0.0; g_ssq[c] = 0.0;
}

// ---------------- norm/elu (+res) + NHWC hi/lo pack (+optional NHWC logits out) ---
__global__ void __launch_bounds__(256)
k_pack_hl(const float* __restrict__ src, const float* __restrict__ res,
          float* __restrict__ outx, __nv_bfloat16* __restrict__ gh,
          __nv_bfloat16* __restrict__ gl, int IC, int do_norm,
          float* __restrict__ outT) {
    __shared__ float s[64][65];
    int tid = threadIdx.x;
    int px0 = blockIdx.x * 64;
    #pragma unroll
    for (int k = 0; k < 16; k++) {
        int idx = k * 256 + tid;
        int c = idx >> 6, px = idx & 63;
        float v = 0.f;
        if (c < IC) {
            v = src[(size_t)c * NPIX + px0 + px];
            if (do_norm) {
                v = (v - g_mean[c]) * g_rstd[c];
                if (res) v += res[(size_t)c * NPIX + px0 + px];
                v = (v > 0.f) ? v : (__expf(v) - 1.f);
            }
            if (outx) outx[(size_t)c * NPIX + px0 + px] = v;
        }
        s[px][c] = v;
    }
    __syncthreads();
    if (outT) {
        float* ob = outT + (size_t)px0 * BINS;
        for (int l = tid; l < 64 * BINS; l += 256) ob[l] = s[l / BINS][l % BINS];
    }
    if (!gh) return;
    #pragma unroll
    for (int k = 0; k < 2; k++) {
        int ch = k * 256 + tid;
        int px = ch >> 3, c0 = (ch & 7) * 8;
        __nv_bfloat16 hh[8], ll[8];
        #pragma unroll
        for (int j = 0; j < 8; j++) {
            float v = s[px][c0 + j];
            hh[j] = __float2bfloat16(v);
            ll[j] = __float2bfloat16(v - __bfloat162float(hh[j]));
        }
        *(uint4*)(gh + ((size_t)(px0 + px)) * 64 + c0) = *(uint4*)hh;
        *(uint4*)(gl + ((size_t)(px0 + px)) * 64 + c0) = *(uint4*)ll;
    }
}

// ---------------- 1x1 input conv ----------------------------------------------------
__global__ void __launch_bounds__(256)
k_conv1x1_in(const float* __restrict__ f, const float* __restrict__ w,
             const float* __restrict__ b, float* __restrict__ out,
             __nv_bfloat16* __restrict__ gh, __nv_bfloat16* __restrict__ gl) {
    __shared__ float sw_[41*64];
    int tid = threadIdx.x;
    for (int idx = tid; idx < 41*64; idx += 256) {
        int ic = idx >> 6, oc = idx & 63;
        sw_[idx] = w[oc*41 + ic];
    }
    __syncthreads();
    int pix = blockIdx.x * 256 + tid;
    float acc[64];
    #pragma unroll
    for (int o = 0; o < 64; o++) acc[o] = b[o];
    const float* fp = f + (size_t)pix * 41;
    for (int ic = 0; ic < 41; ic++) {
        float v = fp[ic];
        #pragma unroll
        for (int o = 0; o < 64; o++) acc[o] += v * sw_[ic*64 + o];
    }
    #pragma unroll
    for (int o = 0; o < 64; o++) out[(size_t)o * NPIX + pix] = acc[o];
    #pragma unroll
    for (int c0 = 0; c0 < 64; c0 += 8) {
        __nv_bfloat16 hh[8], ll[8];
        #pragma unroll
        for (int j = 0; j < 8; j++) {
            float v = acc[c0 + j];
            hh[j] = __float2bfloat16(v);
            ll[j] = __float2bfloat16(v - __bfloat162float(hh[j]));
        }
        *(uint4*)(gh + (size_t)pix * 64 + c0) = *(uint4*)hh;
        *(uint4*)(gl + (size_t)pix * 64 + c0) = *(uint4*)ll;
    }
}

// ---------------- scalar template gate -----------------------------------------------
__global__ void k_gate(const float* __restrict__ td, const float* __restrict__ tq,
                       const float* __restrict__ w1, const float* __restrict__ b1,
                       const float* __restrict__ w2, const float* __restrict__ b2) {
    __shared__ float red[256];
    int t = threadIdx.x;
    float cnt = 0.f;
    for (int i = t; i < NPIX; i += 256) cnt += (td[i] > 0.f) ? 1.f : 0.f;
    red[t] = cnt; __syncthreads();
    for (int st = 128; st > 0; st >>= 1) {
        if (t < st) red[t] += red[t+st];
        __syncthreads();
    }
    if (t == 0) {
        float f0 = red[0] / (float)NPIX, f1 = tq[0], f2 = (float)LL / 512.f;
        float acc = b2[0];
        #pragma unroll
        for (int j = 0; j < 16; j++) {
            float h = f0*w1[j] + f1*w1[16+j] + f2*w1[32+j] + b1[j];
            acc += fmaxf(h, 0.f) * w2[j];
        }
        g_gate = 1.f / (1.f + expf(-acc));
    }
}

// ---------------- anchor projections (right stored [a][k][p]) ---------------------------
__global__ void k_proj_anchor(const float* __restrict__ wl, const float* __restrict__ wr,
                              const float* __restrict__ wvl, const float* __restrict__ wvr) {
    __shared__ float sx[64];
    int p = blockIdx.x, k = blockIdx.y, side = blockIdx.z;
    int ak = k * ASTRIDE;
    int t = threadIdx.x;
    int pix = side == 0 ? p*LL + ak : ak*LL + p;
    sx[t] = g_x[(size_t)t*NPIX + pix];
    __syncthreads();
    if (t < ADIM) {
        const float* w1 = side ? wr  : wl;
        const float* w2 = side ? wvr : wvl;
        float s1 = 0.f, s2 = 0.f;
        #pragma unroll
        for (int c = 0; c < 64; c++) {
            float v = sx[c];
            s1 += v * w1[c*ADIM + t];
            s2 += v * w2[c*ADIM + t];
        }
        if (side) { int o = (t*NANCH + k)*LL + p;   g_right[o] = s1; g_vright[o] = s2; }
        else      { int o = (p*NANCH + k)*ADIM + t; g_left[o]  = s1; g_vleft[o]  = s2; }
    }
}

// ---------------- fused attention ------------------------------------------------------
__global__ void __launch_bounds__(128)
k_attn(const float* __restrict__ td, const float* __restrict__ wq,
       const float* __restrict__ wo, const float* __restrict__ wg,
       const float* __restrict__ bg,
       __nv_bfloat16* __restrict__ gh, __nv_bfloat16* __restrict__ gl) {
    __shared__ float s_l[NANCH*ADIM], s_vl[NANCH*ADIM], s_tl[NANCH];
    __shared__ float s_wq[64*ADIM], s_wo[ADIM*64], s_wg[64*64], s_bg[64];
    int i = blockIdx.y;
    int tid = threadIdx.x;
    for (int idx = tid; idx < NANCH*ADIM; idx += 128) {
        s_l[idx]  = g_left [i*NANCH*ADIM + idx];
        s_vl[idx] = g_vleft[i*NANCH*ADIM + idx];
    }
    for (int idx = tid; idx < 64*ADIM; idx += 128) s_wq[idx] = wq[idx];
    for (int idx = tid; idx < ADIM*64; idx += 128) s_wo[idx] = wo[idx];
    for (int idx = tid; idx < 64*64;  idx += 128) s_wg[idx] = wg[idx];
    if (tid < 64) s_bg[tid] = bg[tid];
    if (tid < NANCH) s_tl[tid] = td[i*LL + tid*ASTRIDE];
    __syncthreads();

    int j = blockIdx.x*128 + tid;
    int pix = i*LL + j;
    float g = g_gate;
    float tdij = td[pix];
    const float invs = 0.1767766952966369f;

    float qv[ADIM];
    #pragma unroll
    for (int a = 0; a < ADIM; a++) qv[a] = 0.f;
    for (int c = 0; c < 64; c++) {
        float xv = g_x[(size_t)c*NPIX + pix];
        #pragma unroll
        for (int a = 0; a < ADIM; a++) qv[a] += xv * s_wq[c*ADIM + a];
    }

    float m = -3.0e38f, ssum = 0.f;
    float acc[ADIM];
    #pragma unroll
    for (int a = 0; a < ADIM; a++) acc[a] = 0.f;

    #pragma unroll 2
    for (int k = 0; k < NANCH; k++) {
        float s = 0.f;
        #pragma unroll
        for (int a = 0; a < ADIM; a++) {
            s += qv[a] * s_l[k*ADIM + a];
            s += qv[a] * g_right[((size_t)a*NANCH + k)*LL + j];
        }
        float ts   = s_tl[k] + td[k*ASTRIDE*LL + j];
        float bias = -fabsf(ts - tdij) * (1.f/12.f);
        s = s*invs + g*bias;
        float mn   = fmaxf(m, s);
        float corr = __expf(m - mn);
        float wgt  = __expf(s - mn);
        ssum = ssum*corr + wgt;
        #pragma unroll
        for (int a = 0; a < ADIM; a++)
            acc[a] = acc[a]*corr +
                     wgt * (s_vl[k*ADIM + a] + g_vright[((size_t)a*NANCH + k)*LL + j]);
        m = mn;
    }
    float inv = 1.f / ssum;
    #pragma unroll
    for (int a = 0; a < ADIM; a++) acc[a] *= inv;

    float pv[64];
    #pragma unroll
    for (int c = 0; c < 64; c++) pv[c] = g_x[(size_t)c*NPIX + pix];

    __nv_bfloat16 hh[8], llb[8];
    for (int c = 0; c < 64; c++) {
        float o = 0.f;
        #pragma unroll
        for (int a = 0; a < ADIM; a++) o += acc[a] * s_wo[a*64 + c];
        float gp = s_bg[c];
        #pragma unroll
        for (int c2 = 0; c2 < 64; c2++) gp += pv[c2] * s_wg[c2*64 + c];
        float gate = fast_sigmoid(gp);
        float nv = pv[c] + gate * o;
        g_x[(size_t)c*NPIX + pix] = nv;
        int jj = c & 7;
        hh[jj]  = __float2bfloat16(nv);
        llb[jj] = __float2bfloat16(nv - __bfloat162float(hh[jj]));
        if (jj == 7) {
            *(uint4*)(gh + (size_t)pix * 64 + (c - 7)) = *(uint4*)hh;
            *(uint4*)(gl + (size_t)pix * 64 + (c - 7)) = *(uint4*)llb;
        }
    }
}

// ---------------- symmetrize (tiled transpose) --------------------------------------
__global__ void k_sym(const float* __restrict__ in, float* __restrict__ out) {
    __shared__ float s2[32][33];
    int c = blockIdx.z;
    int ti = blockIdx.y * 32, tj = blockIdx.x * 32;
    const float* p = in + (size_t)c * NPIX;
    float* o = out + (size_t)c * NPIX;
    int tx = threadIdx.x, ty = threadIdx.y;
    #pragma unroll
    for (int k = 0; k < 4; k++) {
        int r = ty + k * 8;
        s2[r][tx] = p[(size_t)(tj + r) * LL + ti + tx];
    }
    __syncthreads();
    #pragma unroll
    for (int k = 0; k < 4; k++) {
        int r = ty + k * 8;
        o[(size_t)(ti + r) * LL + tj + tx] =
            0.5f * (p[(size_t)(ti + r) * LL + tj + tx] + s2[tx][r]);
    }
}

// ========================================================================================
extern "C" void kernel_launch(void* const* d_in, const int* in_sizes, int n_in,
                              void* d_out, int out_size) {
    const float* features = (const float*)d_in[0];
    const float* td       = (const float*)d_in[1];
    const float* tq       = (const float*)d_in[2];
    const float* in_w     = (const float*)d_in[3];
    const float* in_b     = (const float*)d_in[4];
    const float* c1w      = (const float*)d_in[5];
    const float* c1b      = (const float*)d_in[6];
    const float* c2w      = (const float*)d_in[7];
    const float* c2b      = (const float*)d_in[8];
    const float* wq       = (const float*)d_in[9];
    const float* wl       = (const float*)d_in[10];
    const float* wr       = (const float*)d_in[11];
    const float* wvl      = (const float*)d_in[12];
    const float* wvr      = (const float*)d_in[13];
    const float* wo       = (const float*)d_in[14];
    const float* wg       = (const float*)d_in[15];
    const float* bg       = (const float*)d_in[16];
    const float* tgw1     = (const float*)d_in[17];
    const float* tgb1     = (const float*)d_in[18];
    const float* tgw2     = (const float*)d_in[19];
    const float* tgb2     = (const float*)d_in[20];
    const float* dist_w   = (const float*)d_in[21];
    const float* dist_b   = (const float*)d_in[22];
    const float* cf_w1    = (const float*)d_in[23];
    const float* cf_b1    = (const float*)d_in[24];
    const float* cf_w2    = (const float*)d_in[25];
    const float* cf_b2    = (const float*)d_in[26];
    const float* cf_w3    = (const float*)d_in[27];
    const float* cf_b3    = (const float*)d_in[28];
    float* out = (float*)d_out;

    cudaFuncSetAttribute(k_tconv, cudaFuncAttributeMaxDynamicSharedMemorySize, SMEM_T);

    float *x, *a, *b;
    __nv_bfloat16 *gh, *gl, *wh, *wlo;
    cudaGetSymbolAddress((void**)&x,   g_x);
    cudaGetSymbolAddress((void**)&a,   g_a);
    cudaGetSymbolAddress((void**)&b,   g_b);
    cudaGetSymbolAddress((void**)&gh,  g_h);
    cudaGetSymbolAddress((void**)&gl,  g_l);
    cudaGetSymbolAddress((void**)&wh,  g_wh);
    cudaGetSymbolAddress((void**)&wlo, g_wl);

    const size_t WSL = (size_t)9*64*64;
    dim3 tg(LL, 3);
    const int dil[6] = {1, 2, 4, 8, 16, 1};
    const float* nof = nullptr;

    k_wsplit<<<dim3(9,6), 256>>>(c1w, 0, 64, 64);
    k_wsplit<<<dim3(9,6), 256>>>(c2w, 6, 64, 64);
    k_conv1x1_in<<<NPIX/256, 256>>>(features, in_w, in_b, x, gh, gl);

    for (int i = 0; i < 6; i++) {
        k_tconv<<<tg, 256, SMEM_T>>>(gh, gl, wh + (size_t)i*WSL, wlo + (size_t)i*WSL,
                                     c1b + i*64, a, 64, dil[i], 0, 1, nof, nof);
        k_finstats<<<1, 64>>>();
        k_pack_hl<<<NPIX/64, 256>>>(a, nof, (float*)nullptr, gh, gl, 64, 1, (float*)nullptr);
        k_tconv<<<tg, 256, SMEM_T>>>(gh, gl, wh + (size_t)(6+i)*WSL, wlo + (size_t)(6+i)*WSL,
                                     c2b + i*64, a, 64, 1, 0, 1, nof, nof);
        k_finstats<<<1, 64>>>();
        bool attn = (i & 1);
        k_pack_hl<<<NPIX/64, 256>>>(a, x, x,
                                    attn ? (__nv_bfloat16*)nullptr : gh,
                                    attn ? (__nv_bfloat16*)nullptr : gl, 64, 1, (float*)nullptr);
        if (attn) {
            if (i == 1) k_gate<<<1, 256>>>(td, tq, tgw1, tgb1, tgw2, tgb2);
            k_proj_anchor<<<dim3(LL, NANCH, 2), 64>>>(wl, wr, wvl, wvr);
            k_attn<<<dim3(3, LL), 128>>>(td, wq, wo, wg, bg, gh, gl);
        }
    }

    // distance head (OC=63) + symmetrize
    k_wsplit<<<dim3(9,1), 256>>>(dist_w, 12, 63, 64);
    k_tconv<<<tg, 256, SMEM_T>>>(gh, gl, wh + (size_t)12*WSL, wlo + (size_t)12*WSL,
                                 dist_b, a, 63, 1, 0, 0, nof, nof);
    k_sym<<<dim3(12, 12, BINS), dim3(32, 8)>>>(a, b);

    // confidence head; the pack also emits the NHWC distance logits to out
    k_wsplit<<<dim3(9,1), 256>>>(cf_w1, 13, 32, 63);
    k_wsplit<<<dim3(9,1), 256>>>(cf_w2, 14, 32, 32);
    k_pack_hl<<<NPIX/64, 256>>>(b, nof, (float*)nullptr, gh, gl, 63, 0, out);
    k_tconv<<<tg, 256, SMEM_T>>>(gh, gl, wh + (size_t)13*WSL, wlo + (size_t)13*WSL,
                                 cf_b1, a, 32, 1, 1, 0, nof, nof);
    k_pack_hl<<<NPIX/64, 256>>>(a, nof, (float*)nullptr, gh, gl, 32, 0, (float*)nullptr);
    k_tconv<<<tg, 256, SMEM_T>>>(gh, gl, wh + (size_t)14*WSL, wlo + (size_t)14*WSL,
                                 cf_b2, out, 32, 1, 1, 0, cf_w3, cf_b3);
}